// round 9
// baseline (speedup 1.0000x reference)
#include <cuda_runtime.h>
#include <cuda_fp16.h>
#include <cstdint>
#include <cstddef>

// Problem constants
#define NB      2
#define SQL     4096
#define SKL     4096
#define SQD     512
#define SCD     768
#define NHEADS  8
#define HDIM    64
#define DINNER  512
#define MROWS   (NB*SQL)   // 8192

#define QSCALE  (0.125f * 1.44269504088896340736f)   // dh^-1/2 * log2(e)

// Scratch (allocation-free rule: __device__ globals)
__device__ float  g_Q[(size_t)MROWS * DINNER];   // pre-scaled, tf32, pair-packed dh
__device__ float  g_K[(size_t)MROWS * DINNER];   // tf32, pair-packed dh
__device__ __half g_V[(size_t)MROWS * DINNER];   // fp16
__device__ float  g_A[(size_t)MROWS * DINNER];   // attention out, fp32
__device__ float  g_Wqp[(size_t)SQD * DINNER];   // column-permuted Wq
__device__ float  g_Wkp[(size_t)SCD * DINNER];   // column-permuted Wk

// ---------------------------------------------------------------------------
// helpers
// ---------------------------------------------------------------------------
__device__ __forceinline__ unsigned f2tf(float x) {
    unsigned u;
    asm("cvt.rna.tf32.f32 %0, %1;" : "=r"(u) : "f"(x));
    return u;
}
__device__ __forceinline__ float tf32r(float x) { return __uint_as_float(f2tf(x)); }

__device__ __forceinline__ float ex2(float x) {
    float r;
    asm("ex2.approx.ftz.f32 %0, %1;" : "=f"(r) : "f"(x));
    return r;
}

__device__ __forceinline__ unsigned packh2(float a, float b) {
    __half2 h = __floats2half2_rn(a, b);
    return *reinterpret_cast<unsigned*>(&h);
}

// D = A(16x8, tf32, row) * B(8x8, tf32, col) + C, fp32 accum
__device__ __forceinline__ void mma8(float* c,
                                     unsigned a0, unsigned a1, unsigned a2, unsigned a3,
                                     unsigned b0, unsigned b1) {
    asm volatile(
        "mma.sync.aligned.m16n8k8.row.col.f32.tf32.tf32.f32 "
        "{%0,%1,%2,%3}, {%4,%5,%6,%7}, {%8,%9}, {%0,%1,%2,%3};\n"
        : "+f"(c[0]), "+f"(c[1]), "+f"(c[2]), "+f"(c[3])
        : "r"(a0), "r"(a1), "r"(a2), "r"(a3), "r"(b0), "r"(b1));
}

// D = A(16x16, f16, row) * B(16x8, f16, col) + C, fp32 accum
__device__ __forceinline__ void mma16h(float* c,
                                       unsigned a0, unsigned a1, unsigned a2, unsigned a3,
                                       unsigned b0, unsigned b1) {
    asm volatile(
        "mma.sync.aligned.m16n8k16.row.col.f32.f16.f16.f32 "
        "{%0,%1,%2,%3}, {%4,%5,%6,%7}, {%8,%9}, {%0,%1,%2,%3};\n"
        : "+f"(c[0]), "+f"(c[1]), "+f"(c[2]), "+f"(c[3])
        : "r"(a0), "r"(a1), "r"(a2), "r"(a3), "r"(b0), "r"(b1));
}

__device__ __forceinline__ void ldsm4t(unsigned* r, uint32_t addr) {
    asm volatile(
        "ldmatrix.sync.aligned.m8n8.x4.trans.shared.b16 {%0,%1,%2,%3}, [%4];"
        : "=r"(r[0]), "=r"(r[1]), "=r"(r[2]), "=r"(r[3]) : "r"(addr));
}

#define CP_ASYNC16(dst, src) \
    asm volatile("cp.async.cg.shared.global [%0], [%1], 16;" :: "r"(dst), "l"(src))
#define CP_COMMIT() asm volatile("cp.async.commit_group;")
#define CP_WAIT0()  asm volatile("cp.async.wait_group 0;")

// ---------------------------------------------------------------------------
// Weight column permutation: within each 8-column group, packed position j
// takes original column (j even ? j/2 : j/2 + 4). Applied identically to Wq
// and Wk, QK^T is unchanged, and the GEMM can write plain coalesced float2
// while flash_attn reads (t, t+4) fragment pairs as one LDS.64.
// ---------------------------------------------------------------------------
__global__ __launch_bounds__(256) void permute_w(
    const float* __restrict__ in, float* __restrict__ out, int total)
{
    int idx = blockIdx.x * 256 + threadIdx.x;
    if (idx >= total) return;
    int col = idx & (DINNER - 1);
    int cb = col & ~7, j = col & 7;
    int src = cb + ((j & 1) ? (j >> 1) + 4 : (j >> 1));
    out[idx] = in[(idx - col) + src];
}

// ---------------------------------------------------------------------------
// Generic TF32 GEMM: C[M,N] = A[M,K] @ B[K,N] (+bias), epilogue modes:
//   0: fp32 (+bias if bias != nullptr)
//   1: Q  — scale by QSCALE, tf32 round (weights pre-permuted)
//   2: K  — tf32 round (weights pre-permuted)
//   3: V  — fp16 (half2 stores)
// All modes use coalesced vector stores.
// ---------------------------------------------------------------------------
#define GBM 128
#define GBN 128
#define GBK 16
#define ASTR 20
#define BSTR 136

__global__ __launch_bounds__(256, 2) void gemm_tf32(
    const float* __restrict__ A, const float* __restrict__ B,
    void* __restrict__ Cv, const float* __restrict__ bias,
    int M, int N, int K, int mode)
{
    __shared__ __align__(16) float As[GBM * ASTR];
    __shared__ __align__(16) float Bs[GBK * BSTR];

    const int tid  = threadIdx.x;
    const int warp = tid >> 5, lane = tid & 31;
    const int g = lane >> 2, t = lane & 3;
    const int wm = warp >> 2, wn = warp & 3;
    const int mBase = blockIdx.y * GBM;
    const int nBase = blockIdx.x * GBN;

    float acc[4][4][4];
#pragma unroll
    for (int i = 0; i < 4; i++)
#pragma unroll
        for (int j = 0; j < 4; j++)
#pragma unroll
            for (int c = 0; c < 4; c++) acc[i][j][c] = 0.f;

#pragma unroll 1
    for (int k0 = 0; k0 < K; k0 += GBK) {
#pragma unroll
        for (int i = 0; i < 2; i++) {
            int idx = tid + i * 256;
            int r = idx >> 2, c4 = (idx & 3) * 4;
            float4 v = *(const float4*)(A + (size_t)(mBase + r) * K + k0 + c4);
            v.x = tf32r(v.x); v.y = tf32r(v.y); v.z = tf32r(v.z); v.w = tf32r(v.w);
            *(float4*)(As + r * ASTR + c4) = v;
        }
#pragma unroll
        for (int i = 0; i < 2; i++) {
            int idx = tid + i * 256;
            int r = idx >> 5, c4 = (idx & 31) * 4;
            float4 v = *(const float4*)(B + (size_t)(k0 + r) * N + nBase + c4);
            v.x = tf32r(v.x); v.y = tf32r(v.y); v.z = tf32r(v.z); v.w = tf32r(v.w);
            *(float4*)(Bs + r * BSTR + c4) = v;
        }
        __syncthreads();

#pragma unroll
        for (int kk = 0; kk < 2; kk++) {
            unsigned af[4][4];
#pragma unroll
            for (int mf = 0; mf < 4; mf++) {
                int rb = (wm * 64 + mf * 16 + g) * ASTR + kk * 8 + t;
                af[mf][0] = __float_as_uint(As[rb]);
                af[mf][1] = __float_as_uint(As[rb + 8 * ASTR]);
                af[mf][2] = __float_as_uint(As[rb + 4]);
                af[mf][3] = __float_as_uint(As[rb + 8 * ASTR + 4]);
            }
            unsigned bf[4][2];
#pragma unroll
            for (int nf = 0; nf < 4; nf++) {
                int cb = wn * 32 + nf * 8 + g;
                bf[nf][0] = __float_as_uint(Bs[(kk * 8 + t) * BSTR + cb]);
                bf[nf][1] = __float_as_uint(Bs[(kk * 8 + t + 4) * BSTR + cb]);
            }
#pragma unroll
            for (int mf = 0; mf < 4; mf++)
#pragma unroll
                for (int nf = 0; nf < 4; nf++)
                    mma8(acc[mf][nf], af[mf][0], af[mf][1], af[mf][2], af[mf][3],
                         bf[nf][0], bf[nf][1]);
        }
        __syncthreads();
    }

    // epilogue — all modes coalesced
#pragma unroll
    for (int mf = 0; mf < 4; mf++) {
        int r0 = mBase + wm * 64 + mf * 16 + g;
#pragma unroll
        for (int nf = 0; nf < 4; nf++) {
            int col = nBase + wn * 32 + nf * 8 + 2 * t;
            if (mode == 0) {
                float* C = (float*)Cv;
                float b0 = 0.f, b1 = 0.f;
                if (bias) { b0 = bias[col]; b1 = bias[col + 1]; }
                *(float2*)(C + (size_t)r0 * N + col) =
                    make_float2(acc[mf][nf][0] + b0, acc[mf][nf][1] + b1);
                *(float2*)(C + (size_t)(r0 + 8) * N + col) =
                    make_float2(acc[mf][nf][2] + b0, acc[mf][nf][3] + b1);
            } else if (mode == 3) {
                __half* C = (__half*)Cv;
                *(__half2*)(C + (size_t)r0 * N + col) =
                    __floats2half2_rn(acc[mf][nf][0], acc[mf][nf][1]);
                *(__half2*)(C + (size_t)(r0 + 8) * N + col) =
                    __floats2half2_rn(acc[mf][nf][2], acc[mf][nf][3]);
            } else {
                float* C = (float*)Cv;
                float sc = (mode == 1) ? QSCALE : 1.f;
                *(float2*)(C + (size_t)r0 * N + col) =
                    make_float2(tf32r(acc[mf][nf][0] * sc), tf32r(acc[mf][nf][1] * sc));
                *(float2*)(C + (size_t)(r0 + 8) * N + col) =
                    make_float2(tf32r(acc[mf][nf][2] * sc), tf32r(acc[mf][nf][3] * sc));
            }
        }
    }
}

// ---------------------------------------------------------------------------
// Flash attention v4 (unchanged from R8): 2 CTAs/SM. One CTA = (b, h, 256
// q-rows), 8 warps, M=32 rows/warp, 32-key tiles. Q resident in smem
// (pair-packed tf32, pre-scaled), K/V cp.async double-buffered (K pair-packed
// tf32, V fp16). S via tf32 mma, P->A-frag conversion fully in registers,
// PV via fp16 mma with V B-frags from ldmatrix.trans.
// ---------------------------------------------------------------------------
#define TKEY   32
#define NT     (SKL / TKEY)           // 128 tiles
#define QSTRW  72                     // Q smem row stride, words
#define KSTRW  72                     // K smem row stride, words
#define VSTRH  72                     // V smem row stride, halves
#define QBYTES (256 * QSTRW * 4)      // 73728
#define KBYTES (TKEY * KSTRW * 4)     // 9216
#define VBYTES (TKEY * VSTRH * 2)     // 4608
#define BUFB   (KBYTES + VBYTES)      // 13824
#define ATT_SMEM (QBYTES + 2 * BUFB)  // 101376 bytes

__global__ __launch_bounds__(256, 2) void flash_attn(
    const float* __restrict__ Qg_, const float* __restrict__ Kg_,
    const __half* __restrict__ Vg_, float* __restrict__ O)
{
    extern __shared__ __align__(128) char smc[];
    float* smQf = (float*)smc;
    const uint32_t smem_u32 = (uint32_t)__cvta_generic_to_shared(smc);

    const int tid  = threadIdx.x;
    const int warp = tid >> 5, lane = tid & 31;
    const int g = lane >> 2, t = lane & 3;
    const int h = blockIdx.y, b = blockIdx.z;

    const float*  Qg = Qg_ + ((size_t)b * SQL + blockIdx.x * 256) * DINNER + h * HDIM;
    const float*  Kg = Kg_ + (size_t)b * SKL * DINNER + h * HDIM;
    const __half* Vg = Vg_ + (size_t)b * SKL * DINNER + h * HDIM;
    float*        Ob = O   + ((size_t)b * SQL + blockIdx.x * 256) * DINNER + h * HDIM;

    // ---- async copy Q (256 rows x 256B) ----
#pragma unroll
    for (int i = 0; i < 16; i++) {
        int idx = tid + i * 256;
        int row = idx >> 4, ch = idx & 15;
        CP_ASYNC16(smem_u32 + row * (QSTRW * 4) + ch * 16,
                   Qg + (size_t)row * DINNER + ch * 4);
    }
    // ---- stage K/V tile 0 into buffer 0 ----
    {
        int row = tid >> 4, ch = tid & 15;
        uint32_t kd = smem_u32 + QBYTES;
        CP_ASYNC16(kd + row * (KSTRW * 4) + ch * 16,
                   Kg + (size_t)row * DINNER + ch * 4);
        CP_ASYNC16(kd + (row + 16) * (KSTRW * 4) + ch * 16,
                   Kg + (size_t)(row + 16) * DINNER + ch * 4);
        int vrow = tid >> 3, vch = tid & 7;
        CP_ASYNC16(kd + KBYTES + vrow * (VSTRH * 2) + vch * 16,
                   Vg + (size_t)vrow * DINNER + vch * 8);
    }
    CP_COMMIT();

    // ldmatrix lane geometry for V B-frags
    const int lm_r  = (lane & 7) | (((lane >> 3) & 1) << 3);   // 0..15
    const int lm_c8 = (lane >> 4) << 3;                        // 0 or 8 halves
    const uint32_t vLane = (uint32_t)(lm_r * VSTRH + lm_c8) * 2;

    float oacc[8][8];
#pragma unroll
    for (int nf = 0; nf < 8; nf++)
#pragma unroll
        for (int c = 0; c < 8; c++) oacc[nf][c] = 0.f;

    float mrow[4], lrow[4];
#pragma unroll
    for (int r = 0; r < 4; r++) { mrow[r] = -1e30f; lrow[r] = 0.f; }

    const int qrow = warp * 32 + g;   // local q row (lane's group base)

#pragma unroll 1
    for (int it = 0; it < NT; it++) {
        CP_WAIT0();
        __syncthreads();

        // issue next tile's copies while computing this one
        if (it + 1 < NT) {
            const float*  Kn = Kg + (size_t)(it + 1) * TKEY * DINNER;
            const __half* Vn = Vg + (size_t)(it + 1) * TKEY * DINNER;
            uint32_t kd = smem_u32 + QBYTES + ((it + 1) & 1) * BUFB;
            int row = tid >> 4, ch = tid & 15;
            CP_ASYNC16(kd + row * (KSTRW * 4) + ch * 16,
                       Kn + (size_t)row * DINNER + ch * 4);
            CP_ASYNC16(kd + (row + 16) * (KSTRW * 4) + ch * 16,
                       Kn + (size_t)(row + 16) * DINNER + ch * 4);
            int vrow = tid >> 3, vch = tid & 7;
            CP_ASYNC16(kd + KBYTES + vrow * (VSTRH * 2) + vch * 16,
                       Vn + (size_t)vrow * DINNER + vch * 8);
            CP_COMMIT();
        }

        const float*   Ksm  = (const float*)(smc + QBYTES + (it & 1) * BUFB);
        const uint32_t vbuf = smem_u32 + QBYTES + (it & 1) * BUFB + KBYTES + vLane;

        // ---- S = Q @ K^T : M=32 (2 m16), N=32 keys, K=64 dh (tf32) ----
        float s[4][8];
#pragma unroll
        for (int nf = 0; nf < 4; nf++)
#pragma unroll
            for (int c = 0; c < 8; c++) s[nf][c] = 0.f;
#pragma unroll
        for (int kk = 0; kk < 8; kk++) {
            float2 q00 = *(const float2*)(smQf + (size_t)qrow * QSTRW + kk * 8 + 2 * t);
            float2 q01 = *(const float2*)(smQf + (size_t)(qrow + 8) * QSTRW + kk * 8 + 2 * t);
            float2 q10 = *(const float2*)(smQf + (size_t)(qrow + 16) * QSTRW + kk * 8 + 2 * t);
            float2 q11 = *(const float2*)(smQf + (size_t)(qrow + 24) * QSTRW + kk * 8 + 2 * t);
#pragma unroll
            for (int nf = 0; nf < 4; nf++) {
                float2 kv = *(const float2*)(Ksm + (size_t)(nf * 8 + g) * KSTRW + kk * 8 + 2 * t);
                unsigned b0 = __float_as_uint(kv.x), b1 = __float_as_uint(kv.y);
                mma8(&s[nf][0], __float_as_uint(q00.x), __float_as_uint(q01.x),
                                __float_as_uint(q00.y), __float_as_uint(q01.y), b0, b1);
                mma8(&s[nf][4], __float_as_uint(q10.x), __float_as_uint(q11.x),
                                __float_as_uint(q10.y), __float_as_uint(q11.y), b0, b1);
            }
        }

        // ---- online softmax over 4 row-groups (base-2) ----
        float tm[4];
#pragma unroll
        for (int r = 0; r < 4; r++) tm[r] = -1e30f;
#pragma unroll
        for (int nf = 0; nf < 4; nf++) {
            tm[0] = fmaxf(tm[0], fmaxf(s[nf][0], s[nf][1]));
            tm[1] = fmaxf(tm[1], fmaxf(s[nf][2], s[nf][3]));
            tm[2] = fmaxf(tm[2], fmaxf(s[nf][4], s[nf][5]));
            tm[3] = fmaxf(tm[3], fmaxf(s[nf][6], s[nf][7]));
        }
#pragma unroll
        for (int r = 0; r < 4; r++) {
            tm[r] = fmaxf(tm[r], __shfl_xor_sync(0xffffffffu, tm[r], 1));
            tm[r] = fmaxf(tm[r], __shfl_xor_sync(0xffffffffu, tm[r], 2));
        }
        float nm[4], al[4], rs[4];
#pragma unroll
        for (int r = 0; r < 4; r++) {
            nm[r] = fmaxf(mrow[r], tm[r]);
            al[r] = ex2(mrow[r] - nm[r]);
            rs[r] = 0.f;
        }
#pragma unroll
        for (int nf = 0; nf < 4; nf++) {
            s[nf][0] = ex2(s[nf][0] - nm[0]);
            s[nf][1] = ex2(s[nf][1] - nm[0]);
            s[nf][2] = ex2(s[nf][2] - nm[1]);
            s[nf][3] = ex2(s[nf][3] - nm[1]);
            s[nf][4] = ex2(s[nf][4] - nm[2]);
            s[nf][5] = ex2(s[nf][5] - nm[2]);
            s[nf][6] = ex2(s[nf][6] - nm[3]);
            s[nf][7] = ex2(s[nf][7] - nm[3]);
            rs[0] += s[nf][0] + s[nf][1]; rs[1] += s[nf][2] + s[nf][3];
            rs[2] += s[nf][4] + s[nf][5]; rs[3] += s[nf][6] + s[nf][7];
        }
#pragma unroll
        for (int r = 0; r < 4; r++) {
            rs[r] += __shfl_xor_sync(0xffffffffu, rs[r], 1);
            rs[r] += __shfl_xor_sync(0xffffffffu, rs[r], 2);
            lrow[r] = lrow[r] * al[r] + rs[r];
            mrow[r] = nm[r];
        }
#pragma unroll
        for (int nf = 0; nf < 8; nf++) {
            oacc[nf][0] *= al[0]; oacc[nf][1] *= al[0];
            oacc[nf][2] *= al[1]; oacc[nf][3] *= al[1];
            oacc[nf][4] *= al[2]; oacc[nf][5] *= al[2];
            oacc[nf][6] *= al[3]; oacc[nf][7] *= al[3];
        }

        // ---- O += P @ V : fp16 m16n8k16; A-frags built in registers ----
#pragma unroll
        for (int kk = 0; kk < 2; kk++) {
            unsigned a0 = packh2(s[2*kk][0],     s[2*kk][1]);
            unsigned a1 = packh2(s[2*kk][2],     s[2*kk][3]);
            unsigned a2 = packh2(s[2*kk + 1][0], s[2*kk + 1][1]);
            unsigned a3 = packh2(s[2*kk + 1][2], s[2*kk + 1][3]);
            unsigned a4 = packh2(s[2*kk][4],     s[2*kk][5]);
            unsigned a5 = packh2(s[2*kk][6],     s[2*kk][7]);
            unsigned a6 = packh2(s[2*kk + 1][4], s[2*kk + 1][5]);
            unsigned a7 = packh2(s[2*kk + 1][6], s[2*kk + 1][7]);
            unsigned vb[4][4];
#pragma unroll
            for (int np = 0; np < 4; np++)
                ldsm4t(vb[np], vbuf + kk * (16 * VSTRH * 2) + np * 32);
#pragma unroll
            for (int nf = 0; nf < 8; nf++) {
                unsigned b0 = vb[nf >> 1][(nf & 1) * 2];
                unsigned b1 = vb[nf >> 1][(nf & 1) * 2 + 1];
                mma16h(&oacc[nf][0], a0, a1, a2, a3, b0, b1);
                mma16h(&oacc[nf][4], a4, a5, a6, a7, b0, b1);
            }
        }
    }

    // ---- epilogue: divide by row sums, write fp32 [B, QL, H*DH] ----
    float inv[4];
#pragma unroll
    for (int r = 0; r < 4; r++) inv[r] = 1.0f / lrow[r];
#pragma unroll
    for (int nf = 0; nf < 8; nf++) {
        int col = nf * 8 + 2 * t;
        *(float2*)(Ob + (size_t)qrow * DINNER + col) =
            make_float2(oacc[nf][0] * inv[0], oacc[nf][1] * inv[0]);
        *(float2*)(Ob + (size_t)(qrow + 8) * DINNER + col) =
            make_float2(oacc[nf][2] * inv[1], oacc[nf][3] * inv[1]);
        *(float2*)(Ob + (size_t)(qrow + 16) * DINNER + col) =
            make_float2(oacc[nf][4] * inv[2], oacc[nf][5] * inv[2]);
        *(float2*)(Ob + (size_t)(qrow + 24) * DINNER + col) =
            make_float2(oacc[nf][6] * inv[3], oacc[nf][7] * inv[3]);
    }
}

// ---------------------------------------------------------------------------
// launch
// ---------------------------------------------------------------------------
extern "C" void kernel_launch(void* const* d_in, const int* in_sizes, int n_in,
                              void* d_out, int out_size)
{
    (void)in_sizes; (void)n_in; (void)out_size;
    const float* x   = (const float*)d_in[0];
    const float* ctx = (const float*)d_in[1];
    const float* Wq  = (const float*)d_in[2];
    const float* Wk  = (const float*)d_in[3];
    const float* Wv  = (const float*)d_in[4];
    const float* Wo  = (const float*)d_in[5];
    const float* bo  = (const float*)d_in[6];
    float* out = (float*)d_out;

    float *Qb, *Kb, *Ab, *Wqp, *Wkp;
    __half* Vb;
    cudaGetSymbolAddress((void**)&Qb,  g_Q);
    cudaGetSymbolAddress((void**)&Kb,  g_K);
    cudaGetSymbolAddress((void**)&Vb,  g_V);
    cudaGetSymbolAddress((void**)&Ab,  g_A);
    cudaGetSymbolAddress((void**)&Wqp, g_Wqp);
    cudaGetSymbolAddress((void**)&Wkp, g_Wkp);
    cudaFuncSetAttribute(flash_attn, cudaFuncAttributeMaxDynamicSharedMemorySize,
                         ATT_SMEM);

    dim3 blk(256);
    dim3 gProj(DINNER / GBN, MROWS / GBM);   // (4, 64)

    permute_w<<<(SQD * DINNER + 255) / 256, blk>>>(Wq, Wqp, SQD * DINNER);
    permute_w<<<(SCD * DINNER + 255) / 256, blk>>>(Wk, Wkp, SCD * DINNER);

    gemm_tf32<<<gProj, blk>>>(x,   Wqp, Qb, nullptr, MROWS, DINNER, SQD, 1);
    gemm_tf32<<<gProj, blk>>>(ctx, Wkp, Kb, nullptr, MROWS, DINNER, SCD, 2);
    gemm_tf32<<<gProj, blk>>>(ctx, Wv,  Vb, nullptr, MROWS, DINNER, SCD, 3);
    flash_attn<<<dim3(SQL / 256, NHEADS, NB), blk, ATT_SMEM>>>(Qb, Kb, Vb, Ab);
    gemm_tf32<<<dim3(SQD / GBN, MROWS / GBM), blk>>>(Ab, Wo, out, bo,
                                                     MROWS, SQD, DINNER, 0);
}

// round 10
// speedup vs baseline: 1.0198x; 1.0198x over previous
#include <cuda_runtime.h>
#include <cuda_fp16.h>
#include <cstdint>
#include <cstddef>

// Problem constants
#define NB      2
#define SQL     4096
#define SKL     4096
#define SQD     512
#define SCD     768
#define NHEADS  8
#define HDIM    64
#define DINNER  512
#define MROWS   (NB*SQL)   // 8192

#define QSCALE  (0.125f * 1.44269504088896340736f)   // dh^-1/2 * log2(e)

// Scratch (allocation-free rule: __device__ globals)
__device__ float  g_Q[(size_t)MROWS * DINNER];   // pre-scaled, tf32, pair-packed dh
__device__ float  g_K[(size_t)MROWS * DINNER];   // tf32, pair-packed dh
__device__ __half g_V[(size_t)MROWS * DINNER];   // fp16
__device__ float  g_A[(size_t)MROWS * DINNER];   // attention out (tf32-rounded)
__device__ float  g_X[(size_t)MROWS * SQD];      // tf32-rounded x
__device__ float  g_C[(size_t)MROWS * SCD];      // tf32-rounded context
__device__ float  g_Wqp[(size_t)SQD * DINNER];   // col-permuted + rounded Wq
__device__ float  g_Wkp[(size_t)SCD * DINNER];   // col-permuted + rounded Wk
__device__ float  g_Wvp[(size_t)SCD * DINNER];   // rounded Wv
__device__ float  g_Wop[(size_t)DINNER * SQD];   // rounded Wo

// ---------------------------------------------------------------------------
// helpers
// ---------------------------------------------------------------------------
__device__ __forceinline__ unsigned f2tf(float x) {
    unsigned u;
    asm("cvt.rna.tf32.f32 %0, %1;" : "=r"(u) : "f"(x));
    return u;
}
__device__ __forceinline__ float tf32r(float x) { return __uint_as_float(f2tf(x)); }

__device__ __forceinline__ float ex2(float x) {
    float r;
    asm("ex2.approx.ftz.f32 %0, %1;" : "=f"(r) : "f"(x));
    return r;
}

__device__ __forceinline__ unsigned packh2(float a, float b) {
    __half2 h = __floats2half2_rn(a, b);
    return *reinterpret_cast<unsigned*>(&h);
}

// D = A(16x8, tf32, row) * B(8x8, tf32, col) + C, fp32 accum
__device__ __forceinline__ void mma8(float* c,
                                     unsigned a0, unsigned a1, unsigned a2, unsigned a3,
                                     unsigned b0, unsigned b1) {
    asm volatile(
        "mma.sync.aligned.m16n8k8.row.col.f32.tf32.tf32.f32 "
        "{%0,%1,%2,%3}, {%4,%5,%6,%7}, {%8,%9}, {%0,%1,%2,%3};\n"
        : "+f"(c[0]), "+f"(c[1]), "+f"(c[2]), "+f"(c[3])
        : "r"(a0), "r"(a1), "r"(a2), "r"(a3), "r"(b0), "r"(b1));
}

// D = A(16x16, f16, row) * B(16x8, f16, col) + C, fp32 accum
__device__ __forceinline__ void mma16h(float* c,
                                       unsigned a0, unsigned a1, unsigned a2, unsigned a3,
                                       unsigned b0, unsigned b1) {
    asm volatile(
        "mma.sync.aligned.m16n8k16.row.col.f32.f16.f16.f32 "
        "{%0,%1,%2,%3}, {%4,%5,%6,%7}, {%8,%9}, {%0,%1,%2,%3};\n"
        : "+f"(c[0]), "+f"(c[1]), "+f"(c[2]), "+f"(c[3])
        : "r"(a0), "r"(a1), "r"(a2), "r"(a3), "r"(b0), "r"(b1));
}

__device__ __forceinline__ void ldsm4t(unsigned* r, uint32_t addr) {
    asm volatile(
        "ldmatrix.sync.aligned.m8n8.x4.trans.shared.b16 {%0,%1,%2,%3}, [%4];"
        : "=r"(r[0]), "=r"(r[1]), "=r"(r[2]), "=r"(r[3]) : "r"(addr));
}

#define CP_ASYNC16(dst, src) \
    asm volatile("cp.async.cg.shared.global [%0], [%1], 16;" :: "r"(dst), "l"(src))
#define CP_COMMIT() asm volatile("cp.async.commit_group;")
#define CP_WAIT0()  asm volatile("cp.async.wait_group 0;")
#define CP_WAIT1()  asm volatile("cp.async.wait_group 1;")

// ---------------------------------------------------------------------------
// Pre-pass kernels: tf32 rounding (and optional column pair-pack permute).
// ---------------------------------------------------------------------------
__global__ __launch_bounds__(256) void round4(
    const float* __restrict__ in, float* __restrict__ out, int total4)
{
    int i = blockIdx.x * 256 + threadIdx.x;
    if (i >= total4) return;
    float4 v = ((const float4*)in)[i];
    v.x = tf32r(v.x); v.y = tf32r(v.y); v.z = tf32r(v.z); v.w = tf32r(v.w);
    ((float4*)out)[i] = v;
}

// Within each 8-column group, packed position j takes original column
// (j even ? j/2 : j/2 + 4). Applied identically to Wq and Wk; QK^T unchanged.
__global__ __launch_bounds__(256) void permute_w(
    const float* __restrict__ in, float* __restrict__ out, int total)
{
    int idx = blockIdx.x * 256 + threadIdx.x;
    if (idx >= total) return;
    int col = idx & (DINNER - 1);
    int cb = col & ~7, j = col & 7;
    int src = cb + ((j & 1) ? (j >> 1) + 4 : (j >> 1));
    out[idx] = tf32r(in[(idx - col) + src]);
}

// ---------------------------------------------------------------------------
// TF32 GEMM v2: 3-stage cp.async pipeline, inputs pre-rounded to tf32.
// C[M,N] = A[M,K] @ B[K,N]. Epilogue modes:
//   0: fp32 (+bias)   1: Q (scale QSCALE, tf32)   2: K (tf32)   3: V (fp16)
// BM=128, BN=128, BK=16, 256 threads (8 warps 2x4), warp tile 64x32.
// ---------------------------------------------------------------------------
#define GBM 128
#define GBN 128
#define GBK 16
#define ASTR 20
#define BSTR 136
#define A_STAGE (GBM * ASTR)               // 2560 floats
#define B_STAGE (GBK * BSTR)               // 2176 floats
#define STAGE_F (A_STAGE + B_STAGE)        // 4736 floats
#define STAGE_B (STAGE_F * 4)              // 18944 bytes
#define GEMM_SMEM (3 * STAGE_B)            // 56832 bytes

__global__ __launch_bounds__(256, 2) void gemm_tf32(
    const float* __restrict__ A, const float* __restrict__ B,
    void* __restrict__ Cv, const float* __restrict__ bias,
    int M, int N, int K, int mode)
{
    extern __shared__ __align__(16) float sg[];
    const uint32_t sbase = (uint32_t)__cvta_generic_to_shared(sg);

    const int tid  = threadIdx.x;
    const int warp = tid >> 5, lane = tid & 31;
    const int g = lane >> 2, t = lane & 3;
    const int wm = warp >> 2, wn = warp & 3;
    const int mBase = blockIdx.y * GBM;
    const int nBase = blockIdx.x * GBN;
    const int nK = K / GBK;

    // chunk mapping (2 x 16B chunks per thread for A and for B)
    const int ac0 = tid, ac1 = tid + 256;          // A chunks: row c>>2, off (c&3)*4
    const int bc0 = tid, bc1 = tid + 256;          // B chunks: row c>>5, off (c&31)*4

    float acc[4][4][4];
#pragma unroll
    for (int i = 0; i < 4; i++)
#pragma unroll
        for (int j = 0; j < 4; j++)
#pragma unroll
            for (int c = 0; c < 4; c++) acc[i][j][c] = 0.f;

    // stage issue: copies tile kt into stage buffer s (always commits a group)
    auto issue = [&](int kt, int s) {
        if (kt < nK) {
            const float* Ag = A + (size_t)mBase * K + kt * GBK;
            const float* Bg = B + (size_t)kt * GBK * N + nBase;
            uint32_t as = sbase + s * STAGE_B;
            uint32_t bs = as + A_STAGE * 4;
            CP_ASYNC16(as + ((ac0 >> 2) * ASTR + (ac0 & 3) * 4) * 4,
                       Ag + (size_t)(ac0 >> 2) * K + (ac0 & 3) * 4);
            CP_ASYNC16(as + ((ac1 >> 2) * ASTR + (ac1 & 3) * 4) * 4,
                       Ag + (size_t)(ac1 >> 2) * K + (ac1 & 3) * 4);
            CP_ASYNC16(bs + ((bc0 >> 5) * BSTR + (bc0 & 31) * 4) * 4,
                       Bg + (size_t)(bc0 >> 5) * N + (bc0 & 31) * 4);
            CP_ASYNC16(bs + ((bc1 >> 5) * BSTR + (bc1 & 31) * 4) * 4,
                       Bg + (size_t)(bc1 >> 5) * N + (bc1 & 31) * 4);
        }
        CP_COMMIT();
    };

    issue(0, 0);
    issue(1, 1);

    int s = 0;
#pragma unroll 1
    for (int kt = 0; kt < nK; kt++) {
        CP_WAIT1();            // stage kt arrived
        __syncthreads();       // all warps done with the buffer being re-armed
        issue(kt + 2, (s + 2 >= 3) ? s + 2 - 3 : s + 2);

        const float* As = sg + s * STAGE_F;
        const float* Bs = As + A_STAGE;

#pragma unroll
        for (int kk = 0; kk < 2; kk++) {
            unsigned af[4][4];
#pragma unroll
            for (int mf = 0; mf < 4; mf++) {
                int rb = (wm * 64 + mf * 16 + g) * ASTR + kk * 8 + t;
                af[mf][0] = __float_as_uint(As[rb]);
                af[mf][1] = __float_as_uint(As[rb + 8 * ASTR]);
                af[mf][2] = __float_as_uint(As[rb + 4]);
                af[mf][3] = __float_as_uint(As[rb + 8 * ASTR + 4]);
            }
            unsigned bf[4][2];
#pragma unroll
            for (int nf = 0; nf < 4; nf++) {
                int cb = wn * 32 + nf * 8 + g;
                bf[nf][0] = __float_as_uint(Bs[(kk * 8 + t) * BSTR + cb]);
                bf[nf][1] = __float_as_uint(Bs[(kk * 8 + t + 4) * BSTR + cb]);
            }
#pragma unroll
            for (int mf = 0; mf < 4; mf++)
#pragma unroll
                for (int nf = 0; nf < 4; nf++)
                    mma8(acc[mf][nf], af[mf][0], af[mf][1], af[mf][2], af[mf][3],
                         bf[nf][0], bf[nf][1]);
        }
        s = (s + 1 >= 3) ? 0 : s + 1;
    }

    // epilogue — all modes coalesced
#pragma unroll
    for (int mf = 0; mf < 4; mf++) {
        int r0 = mBase + wm * 64 + mf * 16 + g;
#pragma unroll
        for (int nf = 0; nf < 4; nf++) {
            int col = nBase + wn * 32 + nf * 8 + 2 * t;
            if (mode == 0) {
                float* C = (float*)Cv;
                float b0 = 0.f, b1 = 0.f;
                if (bias) { b0 = bias[col]; b1 = bias[col + 1]; }
                *(float2*)(C + (size_t)r0 * N + col) =
                    make_float2(acc[mf][nf][0] + b0, acc[mf][nf][1] + b1);
                *(float2*)(C + (size_t)(r0 + 8) * N + col) =
                    make_float2(acc[mf][nf][2] + b0, acc[mf][nf][3] + b1);
            } else if (mode == 3) {
                __half* C = (__half*)Cv;
                *(__half2*)(C + (size_t)r0 * N + col) =
                    __floats2half2_rn(acc[mf][nf][0], acc[mf][nf][1]);
                *(__half2*)(C + (size_t)(r0 + 8) * N + col) =
                    __floats2half2_rn(acc[mf][nf][2], acc[mf][nf][3]);
            } else {
                float* C = (float*)Cv;
                float sc = (mode == 1) ? QSCALE : 1.f;
                *(float2*)(C + (size_t)r0 * N + col) =
                    make_float2(tf32r(acc[mf][nf][0] * sc), tf32r(acc[mf][nf][1] * sc));
                *(float2*)(C + (size_t)(r0 + 8) * N + col) =
                    make_float2(tf32r(acc[mf][nf][2] * sc), tf32r(acc[mf][nf][3] * sc));
            }
        }
    }
}

// ---------------------------------------------------------------------------
// Flash attention v4 (proven in R8; epilogue now writes tf32-rounded output
// so the O-projection can cp.async it raw). 2 CTAs/SM. One CTA = (b, h, 256
// q-rows), 8 warps, M=32 rows/warp, 32-key tiles, cp.async double buffer.
// ---------------------------------------------------------------------------
#define TKEY   32
#define NT     (SKL / TKEY)           // 128 tiles
#define QSTRW  72
#define KSTRW  72
#define VSTRH  72
#define QBYTES (256 * QSTRW * 4)      // 73728
#define KBYTES (TKEY * KSTRW * 4)     // 9216
#define VBYTES (TKEY * VSTRH * 2)     // 4608
#define BUFB   (KBYTES + VBYTES)      // 13824
#define ATT_SMEM (QBYTES + 2 * BUFB)  // 101376 bytes

__global__ __launch_bounds__(256, 2) void flash_attn(
    const float* __restrict__ Qg_, const float* __restrict__ Kg_,
    const __half* __restrict__ Vg_, float* __restrict__ O)
{
    extern __shared__ __align__(128) char smc[];
    float* smQf = (float*)smc;
    const uint32_t smem_u32 = (uint32_t)__cvta_generic_to_shared(smc);

    const int tid  = threadIdx.x;
    const int warp = tid >> 5, lane = tid & 31;
    const int g = lane >> 2, t = lane & 3;
    const int h = blockIdx.y, b = blockIdx.z;

    const float*  Qg = Qg_ + ((size_t)b * SQL + blockIdx.x * 256) * DINNER + h * HDIM;
    const float*  Kg = Kg_ + (size_t)b * SKL * DINNER + h * HDIM;
    const __half* Vg = Vg_ + (size_t)b * SKL * DINNER + h * HDIM;
    float*        Ob = O   + ((size_t)b * SQL + blockIdx.x * 256) * DINNER + h * HDIM;

    // ---- async copy Q (256 rows x 256B) ----
#pragma unroll
    for (int i = 0; i < 16; i++) {
        int idx = tid + i * 256;
        int row = idx >> 4, ch = idx & 15;
        CP_ASYNC16(smem_u32 + row * (QSTRW * 4) + ch * 16,
                   Qg + (size_t)row * DINNER + ch * 4);
    }
    // ---- stage K/V tile 0 into buffer 0 ----
    {
        int row = tid >> 4, ch = tid & 15;
        uint32_t kd = smem_u32 + QBYTES;
        CP_ASYNC16(kd + row * (KSTRW * 4) + ch * 16,
                   Kg + (size_t)row * DINNER + ch * 4);
        CP_ASYNC16(kd + (row + 16) * (KSTRW * 4) + ch * 16,
                   Kg + (size_t)(row + 16) * DINNER + ch * 4);
        int vrow = tid >> 3, vch = tid & 7;
        CP_ASYNC16(kd + KBYTES + vrow * (VSTRH * 2) + vch * 16,
                   Vg + (size_t)vrow * DINNER + vch * 8);
    }
    CP_COMMIT();

    const int lm_r  = (lane & 7) | (((lane >> 3) & 1) << 3);
    const int lm_c8 = (lane >> 4) << 3;
    const uint32_t vLane = (uint32_t)(lm_r * VSTRH + lm_c8) * 2;

    float oacc[8][8];
#pragma unroll
    for (int nf = 0; nf < 8; nf++)
#pragma unroll
        for (int c = 0; c < 8; c++) oacc[nf][c] = 0.f;

    float mrow[4], lrow[4];
#pragma unroll
    for (int r = 0; r < 4; r++) { mrow[r] = -1e30f; lrow[r] = 0.f; }

    const int qrow = warp * 32 + g;

#pragma unroll 1
    for (int it = 0; it < NT; it++) {
        CP_WAIT0();
        __syncthreads();

        if (it + 1 < NT) {
            const float*  Kn = Kg + (size_t)(it + 1) * TKEY * DINNER;
            const __half* Vn = Vg + (size_t)(it + 1) * TKEY * DINNER;
            uint32_t kd = smem_u32 + QBYTES + ((it + 1) & 1) * BUFB;
            int row = tid >> 4, ch = tid & 15;
            CP_ASYNC16(kd + row * (KSTRW * 4) + ch * 16,
                       Kn + (size_t)row * DINNER + ch * 4);
            CP_ASYNC16(kd + (row + 16) * (KSTRW * 4) + ch * 16,
                       Kn + (size_t)(row + 16) * DINNER + ch * 4);
            int vrow = tid >> 3, vch = tid & 7;
            CP_ASYNC16(kd + KBYTES + vrow * (VSTRH * 2) + vch * 16,
                       Vn + (size_t)vrow * DINNER + vch * 8);
            CP_COMMIT();
        }

        const float*   Ksm  = (const float*)(smc + QBYTES + (it & 1) * BUFB);
        const uint32_t vbuf = smem_u32 + QBYTES + (it & 1) * BUFB + KBYTES + vLane;

        // ---- S = Q @ K^T ----
        float s[4][8];
#pragma unroll
        for (int nf = 0; nf < 4; nf++)
#pragma unroll
            for (int c = 0; c < 8; c++) s[nf][c] = 0.f;
#pragma unroll
        for (int kk = 0; kk < 8; kk++) {
            float2 q00 = *(const float2*)(smQf + (size_t)qrow * QSTRW + kk * 8 + 2 * t);
            float2 q01 = *(const float2*)(smQf + (size_t)(qrow + 8) * QSTRW + kk * 8 + 2 * t);
            float2 q10 = *(const float2*)(smQf + (size_t)(qrow + 16) * QSTRW + kk * 8 + 2 * t);
            float2 q11 = *(const float2*)(smQf + (size_t)(qrow + 24) * QSTRW + kk * 8 + 2 * t);
#pragma unroll
            for (int nf = 0; nf < 4; nf++) {
                float2 kv = *(const float2*)(Ksm + (size_t)(nf * 8 + g) * KSTRW + kk * 8 + 2 * t);
                unsigned b0 = __float_as_uint(kv.x), b1 = __float_as_uint(kv.y);
                mma8(&s[nf][0], __float_as_uint(q00.x), __float_as_uint(q01.x),
                                __float_as_uint(q00.y), __float_as_uint(q01.y), b0, b1);
                mma8(&s[nf][4], __float_as_uint(q10.x), __float_as_uint(q11.x),
                                __float_as_uint(q10.y), __float_as_uint(q11.y), b0, b1);
            }
        }

        // ---- online softmax (base-2) ----
        float tm[4];
#pragma unroll
        for (int r = 0; r < 4; r++) tm[r] = -1e30f;
#pragma unroll
        for (int nf = 0; nf < 4; nf++) {
            tm[0] = fmaxf(tm[0], fmaxf(s[nf][0], s[nf][1]));
            tm[1] = fmaxf(tm[1], fmaxf(s[nf][2], s[nf][3]));
            tm[2] = fmaxf(tm[2], fmaxf(s[nf][4], s[nf][5]));
            tm[3] = fmaxf(tm[3], fmaxf(s[nf][6], s[nf][7]));
        }
#pragma unroll
        for (int r = 0; r < 4; r++) {
            tm[r] = fmaxf(tm[r], __shfl_xor_sync(0xffffffffu, tm[r], 1));
            tm[r] = fmaxf(tm[r], __shfl_xor_sync(0xffffffffu, tm[r], 2));
        }
        float nm[4], al[4], rs[4];
#pragma unroll
        for (int r = 0; r < 4; r++) {
            nm[r] = fmaxf(mrow[r], tm[r]);
            al[r] = ex2(mrow[r] - nm[r]);
            rs[r] = 0.f;
        }
#pragma unroll
        for (int nf = 0; nf < 4; nf++) {
            s[nf][0] = ex2(s[nf][0] - nm[0]);
            s[nf][1] = ex2(s[nf][1] - nm[0]);
            s[nf][2] = ex2(s[nf][2] - nm[1]);
            s[nf][3] = ex2(s[nf][3] - nm[1]);
            s[nf][4] = ex2(s[nf][4] - nm[2]);
            s[nf][5] = ex2(s[nf][5] - nm[2]);
            s[nf][6] = ex2(s[nf][6] - nm[3]);
            s[nf][7] = ex2(s[nf][7] - nm[3]);
            rs[0] += s[nf][0] + s[nf][1]; rs[1] += s[nf][2] + s[nf][3];
            rs[2] += s[nf][4] + s[nf][5]; rs[3] += s[nf][6] + s[nf][7];
        }
#pragma unroll
        for (int r = 0; r < 4; r++) {
            rs[r] += __shfl_xor_sync(0xffffffffu, rs[r], 1);
            rs[r] += __shfl_xor_sync(0xffffffffu, rs[r], 2);
            lrow[r] = lrow[r] * al[r] + rs[r];
            mrow[r] = nm[r];
        }
#pragma unroll
        for (int nf = 0; nf < 8; nf++) {
            oacc[nf][0] *= al[0]; oacc[nf][1] *= al[0];
            oacc[nf][2] *= al[1]; oacc[nf][3] *= al[1];
            oacc[nf][4] *= al[2]; oacc[nf][5] *= al[2];
            oacc[nf][6] *= al[3]; oacc[nf][7] *= al[3];
        }

        // ---- O += P @ V ----
#pragma unroll
        for (int kk = 0; kk < 2; kk++) {
            unsigned a0 = packh2(s[2*kk][0],     s[2*kk][1]);
            unsigned a1 = packh2(s[2*kk][2],     s[2*kk][3]);
            unsigned a2 = packh2(s[2*kk + 1][0], s[2*kk + 1][1]);
            unsigned a3 = packh2(s[2*kk + 1][2], s[2*kk + 1][3]);
            unsigned a4 = packh2(s[2*kk][4],     s[2*kk][5]);
            unsigned a5 = packh2(s[2*kk][6],     s[2*kk][7]);
            unsigned a6 = packh2(s[2*kk + 1][4], s[2*kk + 1][5]);
            unsigned a7 = packh2(s[2*kk + 1][6], s[2*kk + 1][7]);
            unsigned vb[4][4];
#pragma unroll
            for (int np = 0; np < 4; np++)
                ldsm4t(vb[np], vbuf + kk * (16 * VSTRH * 2) + np * 32);
#pragma unroll
            for (int nf = 0; nf < 8; nf++) {
                unsigned b0 = vb[nf >> 1][(nf & 1) * 2];
                unsigned b1 = vb[nf >> 1][(nf & 1) * 2 + 1];
                mma16h(&oacc[nf][0], a0, a1, a2, a3, b0, b1);
                mma16h(&oacc[nf][4], a4, a5, a6, a7, b0, b1);
            }
        }
    }

    // ---- epilogue: normalize, tf32-round (for raw cp.async in O-proj) ----
    float inv[4];
#pragma unroll
    for (int r = 0; r < 4; r++) inv[r] = 1.0f / lrow[r];
#pragma unroll
    for (int nf = 0; nf < 8; nf++) {
        int col = nf * 8 + 2 * t;
        *(float2*)(Ob + (size_t)qrow * DINNER + col) =
            make_float2(tf32r(oacc[nf][0] * inv[0]), tf32r(oacc[nf][1] * inv[0]));
        *(float2*)(Ob + (size_t)(qrow + 8) * DINNER + col) =
            make_float2(tf32r(oacc[nf][2] * inv[1]), tf32r(oacc[nf][3] * inv[1]));
        *(float2*)(Ob + (size_t)(qrow + 16) * DINNER + col) =
            make_float2(tf32r(oacc[nf][4] * inv[2]), tf32r(oacc[nf][5] * inv[2]));
        *(float2*)(Ob + (size_t)(qrow + 24) * DINNER + col) =
            make_float2(tf32r(oacc[nf][6] * inv[3]), tf32r(oacc[nf][7] * inv[3]));
    }
}

// ---------------------------------------------------------------------------
// launch
// ---------------------------------------------------------------------------
extern "C" void kernel_launch(void* const* d_in, const int* in_sizes, int n_in,
                              void* d_out, int out_size)
{
    (void)in_sizes; (void)n_in; (void)out_size;
    const float* x   = (const float*)d_in[0];
    const float* ctx = (const float*)d_in[1];
    const float* Wq  = (const float*)d_in[2];
    const float* Wk  = (const float*)d_in[3];
    const float* Wv  = (const float*)d_in[4];
    const float* Wo  = (const float*)d_in[5];
    const float* bo  = (const float*)d_in[6];
    float* out = (float*)d_out;

    float *Qb, *Kb, *Ab, *Xb, *Cb, *Wqp, *Wkp, *Wvp, *Wop;
    __half* Vb;
    cudaGetSymbolAddress((void**)&Qb,  g_Q);
    cudaGetSymbolAddress((void**)&Kb,  g_K);
    cudaGetSymbolAddress((void**)&Vb,  g_V);
    cudaGetSymbolAddress((void**)&Ab,  g_A);
    cudaGetSymbolAddress((void**)&Xb,  g_X);
    cudaGetSymbolAddress((void**)&Cb,  g_C);
    cudaGetSymbolAddress((void**)&Wqp, g_Wqp);
    cudaGetSymbolAddress((void**)&Wkp, g_Wkp);
    cudaGetSymbolAddress((void**)&Wvp, g_Wvp);
    cudaGetSymbolAddress((void**)&Wop, g_Wop);
    cudaFuncSetAttribute(flash_attn, cudaFuncAttributeMaxDynamicSharedMemorySize,
                         ATT_SMEM);
    cudaFuncSetAttribute(gemm_tf32, cudaFuncAttributeMaxDynamicSharedMemorySize,
                         GEMM_SMEM);

    dim3 blk(256);
    dim3 gProj(DINNER / GBN, MROWS / GBM);   // (4, 64)

    // pre-passes: tf32-round inputs/weights (permute_w also rounds)
    round4<<<(MROWS * SQD / 4 + 255) / 256, blk>>>(x,   Xb, MROWS * SQD / 4);
    round4<<<(MROWS * SCD / 4 + 255) / 256, blk>>>(ctx, Cb, MROWS * SCD / 4);
    round4<<<(SCD * DINNER / 4 + 255) / 256, blk>>>(Wv, Wvp, SCD * DINNER / 4);
    round4<<<(DINNER * SQD / 4 + 255) / 256, blk>>>(Wo, Wop, DINNER * SQD / 4);
    permute_w<<<(SQD * DINNER + 255) / 256, blk>>>(Wq, Wqp, SQD * DINNER);
    permute_w<<<(SCD * DINNER + 255) / 256, blk>>>(Wk, Wkp, SCD * DINNER);

    gemm_tf32<<<gProj, blk, GEMM_SMEM>>>(Xb, Wqp, Qb, nullptr, MROWS, DINNER, SQD, 1);
    gemm_tf32<<<gProj, blk, GEMM_SMEM>>>(Cb, Wkp, Kb, nullptr, MROWS, DINNER, SCD, 2);
    gemm_tf32<<<gProj, blk, GEMM_SMEM>>>(Cb, Wvp, Vb, nullptr, MROWS, DINNER, SCD, 3);
    flash_attn<<<dim3(SQL / 256, NHEADS, NB), blk, ATT_SMEM>>>(Qb, Kb, Vb, Ab);
    gemm_tf32<<<dim3(SQD / GBN, MROWS / GBM), blk, GEMM_SMEM>>>(
        Ab, Wop, out, bo, MROWS, SQD, DINNER, 0);
}

// round 15
// speedup vs baseline: 1.3301x; 1.3043x over previous
#include <cuda_runtime.h>
#include <cuda_fp16.h>
#include <cstdint>
#include <cstddef>

// Problem constants
#define NB      2
#define SQL     4096
#define SKL     4096
#define SQD     512
#define SCD     768
#define NHEADS  8
#define HDIM    64
#define DINNER  512
#define MROWS   (NB*SQL)   // 8192

#define QSCALE  (0.125f * 1.44269504088896340736f)   // dh^-1/2 * log2(e)

// Scratch (allocation-free rule: __device__ globals)
__device__ __half g_Q[(size_t)MROWS * DINNER];   // fp16, pre-scaled by QSCALE
__device__ __half g_K[(size_t)MROWS * DINNER];   // fp16
__device__ __half g_V[(size_t)MROWS * DINNER];   // fp16
__device__ float  g_A[(size_t)MROWS * DINNER];   // attention out (tf32-rounded)
__device__ float  g_X[(size_t)MROWS * SQD];      // tf32-rounded x
__device__ float  g_C[(size_t)MROWS * SCD];      // tf32-rounded context
__device__ float  g_Wqp[(size_t)SQD * DINNER];   // tf32-rounded Wq
__device__ float  g_Wkp[(size_t)SCD * DINNER];   // tf32-rounded Wk
__device__ float  g_Wvp[(size_t)SCD * DINNER];   // tf32-rounded Wv
__device__ float  g_Wop[(size_t)DINNER * SQD];   // tf32-rounded Wo

// ---------------------------------------------------------------------------
// helpers
// ---------------------------------------------------------------------------
__device__ __forceinline__ unsigned f2tf(float x) {
    unsigned u;
    asm("cvt.rna.tf32.f32 %0, %1;" : "=r"(u) : "f"(x));
    return u;
}
__device__ __forceinline__ float tf32r(float x) { return __uint_as_float(f2tf(x)); }

__device__ __forceinline__ float ex2(float x) {
    float r;
    asm("ex2.approx.ftz.f32 %0, %1;" : "=f"(r) : "f"(x));
    return r;
}

__device__ __forceinline__ unsigned packh2(float a, float b) {
    __half2 h = __floats2half2_rn(a, b);
    return *reinterpret_cast<unsigned*>(&h);
}

// D = A(16x8, tf32, row) * B(8x8, tf32, col) + C, fp32 accum
__device__ __forceinline__ void mma8(float* c,
                                     unsigned a0, unsigned a1, unsigned a2, unsigned a3,
                                     unsigned b0, unsigned b1) {
    asm volatile(
        "mma.sync.aligned.m16n8k8.row.col.f32.tf32.tf32.f32 "
        "{%0,%1,%2,%3}, {%4,%5,%6,%7}, {%8,%9}, {%0,%1,%2,%3};\n"
        : "+f"(c[0]), "+f"(c[1]), "+f"(c[2]), "+f"(c[3])
        : "r"(a0), "r"(a1), "r"(a2), "r"(a3), "r"(b0), "r"(b1));
}

// D = A(16x16, f16, row) * B(16x8, f16, col) + C, fp32 accum
__device__ __forceinline__ void mma16h(float* c,
                                       unsigned a0, unsigned a1, unsigned a2, unsigned a3,
                                       unsigned b0, unsigned b1) {
    asm volatile(
        "mma.sync.aligned.m16n8k16.row.col.f32.f16.f16.f32 "
        "{%0,%1,%2,%3}, {%4,%5,%6,%7}, {%8,%9}, {%0,%1,%2,%3};\n"
        : "+f"(c[0]), "+f"(c[1]), "+f"(c[2]), "+f"(c[3])
        : "r"(a0), "r"(a1), "r"(a2), "r"(a3), "r"(b0), "r"(b1));
}

__device__ __forceinline__ void ldsm4(unsigned* r, uint32_t addr) {
    asm volatile(
        "ldmatrix.sync.aligned.m8n8.x4.shared.b16 {%0,%1,%2,%3}, [%4];"
        : "=r"(r[0]), "=r"(r[1]), "=r"(r[2]), "=r"(r[3]) : "r"(addr));
}
__device__ __forceinline__ void ldsm4t(unsigned* r, uint32_t addr) {
    asm volatile(
        "ldmatrix.sync.aligned.m8n8.x4.trans.shared.b16 {%0,%1,%2,%3}, [%4];"
        : "=r"(r[0]), "=r"(r[1]), "=r"(r[2]), "=r"(r[3]) : "r"(addr));
}

#define CP_ASYNC16(dst, src) \
    asm volatile("cp.async.cg.shared.global [%0], [%1], 16;" :: "r"(dst), "l"(src))
#define CP_COMMIT() asm volatile("cp.async.commit_group;")
#define CP_WAIT0()  asm volatile("cp.async.wait_group 0;")
#define CP_WAIT1()  asm volatile("cp.async.wait_group 1;")

// ---------------------------------------------------------------------------
// Pre-pass: tf32 rounding (GEMM operands are cp.async'd raw).
// ---------------------------------------------------------------------------
__global__ __launch_bounds__(256) void round4(
    const float* __restrict__ in, float* __restrict__ out, int total4)
{
    int i = blockIdx.x * 256 + threadIdx.x;
    if (i >= total4) return;
    float4 v = ((const float4*)in)[i];
    v.x = tf32r(v.x); v.y = tf32r(v.y); v.z = tf32r(v.z); v.w = tf32r(v.w);
    ((float4*)out)[i] = v;
}

// ---------------------------------------------------------------------------
// TF32 GEMM: 3-stage cp.async pipeline, inputs pre-rounded to tf32.
// C[M,N] = A[M,K] @ B[K,N]. Epilogue modes:
//   0: fp32 (+bias)   1: fp16 scaled by QSCALE (Q)   2: fp16 (K, V)
// BM=128, BN=128, BK=16, 256 threads (8 warps 2x4), warp tile 64x32.
// ---------------------------------------------------------------------------
#define GBM 128
#define GBN 128
#define GBK 16
#define ASTR 20
#define BSTR 136
#define A_STAGE (GBM * ASTR)               // 2560 floats
#define B_STAGE (GBK * BSTR)               // 2176 floats
#define STAGE_F (A_STAGE + B_STAGE)        // 4736 floats
#define STAGE_B (STAGE_F * 4)              // 18944 bytes
#define GEMM_SMEM (3 * STAGE_B)            // 56832 bytes

__global__ __launch_bounds__(256, 2) void gemm_tf32(
    const float* __restrict__ A, const float* __restrict__ B,
    void* __restrict__ Cv, const float* __restrict__ bias,
    int M, int N, int K, int mode)
{
    extern __shared__ __align__(16) float sg[];
    const uint32_t sbase = (uint32_t)__cvta_generic_to_shared(sg);

    const int tid  = threadIdx.x;
    const int warp = tid >> 5, lane = tid & 31;
    const int g = lane >> 2, t = lane & 3;
    const int wm = warp >> 2, wn = warp & 3;
    const int mBase = blockIdx.y * GBM;
    const int nBase = blockIdx.x * GBN;
    const int nK = K / GBK;

    const int ac0 = tid, ac1 = tid + 256;
    const int bc0 = tid, bc1 = tid + 256;

    float acc[4][4][4];
#pragma unroll
    for (int i = 0; i < 4; i++)
#pragma unroll
        for (int j = 0; j < 4; j++)
#pragma unroll
            for (int c = 0; c < 4; c++) acc[i][j][c] = 0.f;

    auto issue = [&](int kt, int s) {
        if (kt < nK) {
            const float* Ag = A + (size_t)mBase * K + kt * GBK;
            const float* Bg = B + (size_t)kt * GBK * N + nBase;
            uint32_t as = sbase + s * STAGE_B;
            uint32_t bs = as + A_STAGE * 4;
            CP_ASYNC16(as + ((ac0 >> 2) * ASTR + (ac0 & 3) * 4) * 4,
                       Ag + (size_t)(ac0 >> 2) * K + (ac0 & 3) * 4);
            CP_ASYNC16(as + ((ac1 >> 2) * ASTR + (ac1 & 3) * 4) * 4,
                       Ag + (size_t)(ac1 >> 2) * K + (ac1 & 3) * 4);
            CP_ASYNC16(bs + ((bc0 >> 5) * BSTR + (bc0 & 31) * 4) * 4,
                       Bg + (size_t)(bc0 >> 5) * N + (bc0 & 31) * 4);
            CP_ASYNC16(bs + ((bc1 >> 5) * BSTR + (bc1 & 31) * 4) * 4,
                       Bg + (size_t)(bc1 >> 5) * N + (bc1 & 31) * 4);
        }
        CP_COMMIT();
    };

    issue(0, 0);
    issue(1, 1);

    int s = 0;
#pragma unroll 1
    for (int kt = 0; kt < nK; kt++) {
        CP_WAIT1();
        __syncthreads();
        issue(kt + 2, (s + 2 >= 3) ? s + 2 - 3 : s + 2);

        const float* As = sg + s * STAGE_F;
        const float* Bs = As + A_STAGE;

#pragma unroll
        for (int kk = 0; kk < 2; kk++) {
            unsigned af[4][4];
#pragma unroll
            for (int mf = 0; mf < 4; mf++) {
                int rb = (wm * 64 + mf * 16 + g) * ASTR + kk * 8 + t;
                af[mf][0] = __float_as_uint(As[rb]);
                af[mf][1] = __float_as_uint(As[rb + 8 * ASTR]);
                af[mf][2] = __float_as_uint(As[rb + 4]);
                af[mf][3] = __float_as_uint(As[rb + 8 * ASTR + 4]);
            }
            unsigned bf[4][2];
#pragma unroll
            for (int nf = 0; nf < 4; nf++) {
                int cb = wn * 32 + nf * 8 + g;
                bf[nf][0] = __float_as_uint(Bs[(kk * 8 + t) * BSTR + cb]);
                bf[nf][1] = __float_as_uint(Bs[(kk * 8 + t + 4) * BSTR + cb]);
            }
#pragma unroll
            for (int mf = 0; mf < 4; mf++)
#pragma unroll
                for (int nf = 0; nf < 4; nf++)
                    mma8(acc[mf][nf], af[mf][0], af[mf][1], af[mf][2], af[mf][3],
                         bf[nf][0], bf[nf][1]);
        }
        s = (s + 1 >= 3) ? 0 : s + 1;
    }

    // epilogue
#pragma unroll
    for (int mf = 0; mf < 4; mf++) {
        int r0 = mBase + wm * 64 + mf * 16 + g;
#pragma unroll
        for (int nf = 0; nf < 4; nf++) {
            int col = nBase + wn * 32 + nf * 8 + 2 * t;
            if (mode == 0) {
                float* C = (float*)Cv;
                float b0 = 0.f, b1 = 0.f;
                if (bias) { b0 = bias[col]; b1 = bias[col + 1]; }
                *(float2*)(C + (size_t)r0 * N + col) =
                    make_float2(acc[mf][nf][0] + b0, acc[mf][nf][1] + b1);
                *(float2*)(C + (size_t)(r0 + 8) * N + col) =
                    make_float2(acc[mf][nf][2] + b0, acc[mf][nf][3] + b1);
            } else {
                __half* C = (__half*)Cv;
                float sc = (mode == 1) ? QSCALE : 1.f;
                *(__half2*)(C + (size_t)r0 * N + col) =
                    __floats2half2_rn(acc[mf][nf][0] * sc, acc[mf][nf][1] * sc);
                *(__half2*)(C + (size_t)(r0 + 8) * N + col) =
                    __floats2half2_rn(acc[mf][nf][2] * sc, acc[mf][nf][3] * sc);
            }
        }
    }
}

// ---------------------------------------------------------------------------
// Flash attention v5 (fixed): all-fp16 operands, all-ldmatrix fragment loads.
// K B-frags use NON-trans ldmatrix: K smem is [key][dh] = [n][k], which is
// exactly the .col layout mma expects (thread(g,t) <- K[g][2t..2t+1]).
// V B-frags keep trans ldmatrix: V smem is [key][dh] = [k][n].
// 2 CTAs/SM. One CTA = (b, h, 256 q-rows), 8 warps, M=32 rows/warp,
// 32-key tiles, cp.async double buffer, softmax in log2 domain.
// ---------------------------------------------------------------------------
#define TKEY   32
#define NT     (SKL / TKEY)            // 128 tiles
#define QSTRH  72                      // Q smem row stride (halves)
#define KSTRH  72                      // K tile row stride (halves)
#define VSTRH  72                      // V tile row stride (halves)
#define QBYTES (256 * QSTRH * 2)       // 36864
#define KBYTES (TKEY * KSTRH * 2)      // 4608
#define VBYTES (TKEY * VSTRH * 2)      // 4608
#define BUFB   (KBYTES + VBYTES)       // 9216
#define ATT_SMEM (QBYTES + 2 * BUFB)   // 55296 bytes

__global__ __launch_bounds__(256, 2) void flash_attn(
    const __half* __restrict__ Qg_, const __half* __restrict__ Kg_,
    const __half* __restrict__ Vg_, float* __restrict__ O)
{
    extern __shared__ __align__(128) char smc[];
    const uint32_t smem_u32 = (uint32_t)__cvta_generic_to_shared(smc);

    const int tid  = threadIdx.x;
    const int warp = tid >> 5, lane = tid & 31;
    const int t = lane & 3;
    const int h = blockIdx.y, b = blockIdx.z;

    const __half* Qg = Qg_ + ((size_t)b * SQL + blockIdx.x * 256) * DINNER + h * HDIM;
    const __half* Kg = Kg_ + (size_t)b * SKL * DINNER + h * HDIM;
    const __half* Vg = Vg_ + (size_t)b * SKL * DINNER + h * HDIM;
    float*        Ob = O   + ((size_t)b * SQL + blockIdx.x * 256) * DINNER + h * HDIM;

    // ---- async copy Q (256 rows x 128B) ----
#pragma unroll
    for (int i = 0; i < 8; i++) {
        int idx = tid + i * 256;
        int row = idx >> 3, ch = idx & 7;
        CP_ASYNC16(smem_u32 + row * (QSTRH * 2) + ch * 16,
                   Qg + (size_t)row * DINNER + ch * 8);
    }
    // ---- stage K/V tile 0 into buffer 0 ----
    {
        int row = tid >> 3, ch = tid & 7;
        uint32_t kd = smem_u32 + QBYTES;
        CP_ASYNC16(kd + row * (KSTRH * 2) + ch * 16,
                   Kg + (size_t)row * DINNER + ch * 8);
        CP_ASYNC16(kd + KBYTES + row * (VSTRH * 2) + ch * 16,
                   Vg + (size_t)row * DINNER + ch * 8);
    }
    CP_COMMIT();

    // ldmatrix lane geometry (shared by A non-trans, B non-trans, B trans)
    const int lm_r  = (lane & 7) | (((lane >> 3) & 1) << 3);   // 0..15
    const int lm_c8 = (lane >> 4) << 3;                        // 0 or 8 halves
    const uint32_t qA0 = smem_u32 + ((warp * 32 + lm_r) * QSTRH + lm_c8) * 2;
    const uint32_t qA1 = qA0 + 16 * QSTRH * 2;
    const uint32_t kLane = (uint32_t)(lm_r * KSTRH + lm_c8) * 2;
    const uint32_t vLane = (uint32_t)(lm_r * VSTRH + lm_c8) * 2;

    float oacc[8][8];
#pragma unroll
    for (int nf = 0; nf < 8; nf++)
#pragma unroll
        for (int c = 0; c < 8; c++) oacc[nf][c] = 0.f;

    float mrow[4], lrow[4];
#pragma unroll
    for (int r = 0; r < 4; r++) { mrow[r] = -1e30f; lrow[r] = 0.f; }

    const int qrow = warp * 32 + (lane >> 2);   // epilogue row indexing

#pragma unroll 1
    for (int it = 0; it < NT; it++) {
        CP_WAIT0();
        __syncthreads();

        if (it + 1 < NT) {
            const __half* Kn = Kg + (size_t)(it + 1) * TKEY * DINNER;
            const __half* Vn = Vg + (size_t)(it + 1) * TKEY * DINNER;
            uint32_t kd = smem_u32 + QBYTES + ((it + 1) & 1) * BUFB;
            int row = tid >> 3, ch = tid & 7;
            CP_ASYNC16(kd + row * (KSTRH * 2) + ch * 16,
                       Kn + (size_t)row * DINNER + ch * 8);
            CP_ASYNC16(kd + KBYTES + row * (VSTRH * 2) + ch * 16,
                       Vn + (size_t)row * DINNER + ch * 8);
            CP_COMMIT();
        }

        const uint32_t kbuf = smem_u32 + QBYTES + (it & 1) * BUFB + kLane;
        const uint32_t vbuf = smem_u32 + QBYTES + (it & 1) * BUFB + KBYTES + vLane;

        // ---- S = Q @ K^T : fp16 m16n8k16, M=32, N=32 keys, K=64 dh ----
        // K via NON-trans ldmatrix; x4 result order:
        //   r0 = keys 0-7 / dh-lo, r1 = keys 8-15 / dh-lo,
        //   r2 = keys 0-7 / dh-hi, r3 = keys 8-15 / dh-hi
        float s[4][8];
#pragma unroll
        for (int nf = 0; nf < 4; nf++)
#pragma unroll
            for (int c = 0; c < 8; c++) s[nf][c] = 0.f;
#pragma unroll
        for (int kk = 0; kk < 4; kk++) {
            unsigned qa0[4], qa1[4], kb[2][4];
            ldsm4(qa0, qA0 + kk * 32);
            ldsm4(qa1, qA1 + kk * 32);
            ldsm4(kb[0], kbuf + kk * 32);                       // keys 0-15
            ldsm4(kb[1], kbuf + 16 * KSTRH * 2 + kk * 32);      // keys 16-31
#pragma unroll
            for (int nf = 0; nf < 4; nf++) {
                unsigned b0 = kb[nf >> 1][nf & 1];              // dh-lo 8
                unsigned b1 = kb[nf >> 1][(nf & 1) + 2];        // dh-hi 8
                mma16h(&s[nf][0], qa0[0], qa0[1], qa0[2], qa0[3], b0, b1);
                mma16h(&s[nf][4], qa1[0], qa1[1], qa1[2], qa1[3], b0, b1);
            }
        }

        // ---- online softmax over 4 row-groups (base-2) ----
        float tm[4];
#pragma unroll
        for (int r = 0; r < 4; r++) tm[r] = -1e30f;
#pragma unroll
        for (int nf = 0; nf < 4; nf++) {
            tm[0] = fmaxf(tm[0], fmaxf(s[nf][0], s[nf][1]));
            tm[1] = fmaxf(tm[1], fmaxf(s[nf][2], s[nf][3]));
            tm[2] = fmaxf(tm[2], fmaxf(s[nf][4], s[nf][5]));
            tm[3] = fmaxf(tm[3], fmaxf(s[nf][6], s[nf][7]));
        }
#pragma unroll
        for (int r = 0; r < 4; r++) {
            tm[r] = fmaxf(tm[r], __shfl_xor_sync(0xffffffffu, tm[r], 1));
            tm[r] = fmaxf(tm[r], __shfl_xor_sync(0xffffffffu, tm[r], 2));
        }
        float nm[4], al[4], rs[4];
#pragma unroll
        for (int r = 0; r < 4; r++) {
            nm[r] = fmaxf(mrow[r], tm[r]);
            al[r] = ex2(mrow[r] - nm[r]);
            rs[r] = 0.f;
        }
#pragma unroll
        for (int nf = 0; nf < 4; nf++) {
            s[nf][0] = ex2(s[nf][0] - nm[0]);
            s[nf][1] = ex2(s[nf][1] - nm[0]);
            s[nf][2] = ex2(s[nf][2] - nm[1]);
            s[nf][3] = ex2(s[nf][3] - nm[1]);
            s[nf][4] = ex2(s[nf][4] - nm[2]);
            s[nf][5] = ex2(s[nf][5] - nm[2]);
            s[nf][6] = ex2(s[nf][6] - nm[3]);
            s[nf][7] = ex2(s[nf][7] - nm[3]);
            rs[0] += s[nf][0] + s[nf][1]; rs[1] += s[nf][2] + s[nf][3];
            rs[2] += s[nf][4] + s[nf][5]; rs[3] += s[nf][6] + s[nf][7];
        }
#pragma unroll
        for (int r = 0; r < 4; r++) {
            rs[r] += __shfl_xor_sync(0xffffffffu, rs[r], 1);
            rs[r] += __shfl_xor_sync(0xffffffffu, rs[r], 2);
            lrow[r] = lrow[r] * al[r] + rs[r];
            mrow[r] = nm[r];
        }
#pragma unroll
        for (int nf = 0; nf < 8; nf++) {
            oacc[nf][0] *= al[0]; oacc[nf][1] *= al[0];
            oacc[nf][2] *= al[1]; oacc[nf][3] *= al[1];
            oacc[nf][4] *= al[2]; oacc[nf][5] *= al[2];
            oacc[nf][6] *= al[3]; oacc[nf][7] *= al[3];
        }

        // ---- O += P @ V : fp16 m16n8k16; P A-frags built in registers ----
#pragma unroll
        for (int kk = 0; kk < 2; kk++) {
            unsigned a0 = packh2(s[2*kk][0],     s[2*kk][1]);
            unsigned a1 = packh2(s[2*kk][2],     s[2*kk][3]);
            unsigned a2 = packh2(s[2*kk + 1][0], s[2*kk + 1][1]);
            unsigned a3 = packh2(s[2*kk + 1][2], s[2*kk + 1][3]);
            unsigned a4 = packh2(s[2*kk][4],     s[2*kk][5]);
            unsigned a5 = packh2(s[2*kk][6],     s[2*kk][7]);
            unsigned a6 = packh2(s[2*kk + 1][4], s[2*kk + 1][5]);
            unsigned a7 = packh2(s[2*kk + 1][6], s[2*kk + 1][7]);
            unsigned vb[4][4];
#pragma unroll
            for (int np = 0; np < 4; np++)
                ldsm4t(vb[np], vbuf + kk * (16 * VSTRH * 2) + np * 32);
#pragma unroll
            for (int nf = 0; nf < 8; nf++) {
                unsigned b0 = vb[nf >> 1][(nf & 1) * 2];
                unsigned b1 = vb[nf >> 1][(nf & 1) * 2 + 1];
                mma16h(&oacc[nf][0], a0, a1, a2, a3, b0, b1);
                mma16h(&oacc[nf][4], a4, a5, a6, a7, b0, b1);
            }
        }
    }

    // ---- epilogue: normalize, tf32-round (O-proj cp.asyncs this raw) ----
    float inv[4];
#pragma unroll
    for (int r = 0; r < 4; r++) inv[r] = 1.0f / lrow[r];
#pragma unroll
    for (int nf = 0; nf < 8; nf++) {
        int col = nf * 8 + 2 * t;
        *(float2*)(Ob + (size_t)qrow * DINNER + col) =
            make_float2(tf32r(oacc[nf][0] * inv[0]), tf32r(oacc[nf][1] * inv[0]));
        *(float2*)(Ob + (size_t)(qrow + 8) * DINNER + col) =
            make_float2(tf32r(oacc[nf][2] * inv[1]), tf32r(oacc[nf][3] * inv[1]));
        *(float2*)(Ob + (size_t)(qrow + 16) * DINNER + col) =
            make_float2(tf32r(oacc[nf][4] * inv[2]), tf32r(oacc[nf][5] * inv[2]));
        *(float2*)(Ob + (size_t)(qrow + 24) * DINNER + col) =
            make_float2(tf32r(oacc[nf][6] * inv[3]), tf32r(oacc[nf][7] * inv[3]));
    }
}

// ---------------------------------------------------------------------------
// launch
// ---------------------------------------------------------------------------
extern "C" void kernel_launch(void* const* d_in, const int* in_sizes, int n_in,
                              void* d_out, int out_size)
{
    (void)in_sizes; (void)n_in; (void)out_size;
    const float* x   = (const float*)d_in[0];
    const float* ctx = (const float*)d_in[1];
    const float* Wq  = (const float*)d_in[2];
    const float* Wk  = (const float*)d_in[3];
    const float* Wv  = (const float*)d_in[4];
    const float* Wo  = (const float*)d_in[5];
    const float* bo  = (const float*)d_in[6];
    float* out = (float*)d_out;

    float *Ab, *Xb, *Cb, *Wqp, *Wkp, *Wvp, *Wop;
    __half *Qb, *Kb, *Vb;
    cudaGetSymbolAddress((void**)&Qb,  g_Q);
    cudaGetSymbolAddress((void**)&Kb,  g_K);
    cudaGetSymbolAddress((void**)&Vb,  g_V);
    cudaGetSymbolAddress((void**)&Ab,  g_A);
    cudaGetSymbolAddress((void**)&Xb,  g_X);
    cudaGetSymbolAddress((void**)&Cb,  g_C);
    cudaGetSymbolAddress((void**)&Wqp, g_Wqp);
    cudaGetSymbolAddress((void**)&Wkp, g_Wkp);
    cudaGetSymbolAddress((void**)&Wvp, g_Wvp);
    cudaGetSymbolAddress((void**)&Wop, g_Wop);
    cudaFuncSetAttribute(flash_attn, cudaFuncAttributeMaxDynamicSharedMemorySize,
                         ATT_SMEM);
    cudaFuncSetAttribute(gemm_tf32, cudaFuncAttributeMaxDynamicSharedMemorySize,
                         GEMM_SMEM);

    dim3 blk(256);
    dim3 gProj(DINNER / GBN, MROWS / GBM);   // (4, 64)

    // pre-passes: tf32-round inputs/weights
    round4<<<(MROWS * SQD / 4 + 255) / 256, blk>>>(x,   Xb, MROWS * SQD / 4);
    round4<<<(MROWS * SCD / 4 + 255) / 256, blk>>>(ctx, Cb, MROWS * SCD / 4);
    round4<<<(SQD * DINNER / 4 + 255) / 256, blk>>>(Wq, Wqp, SQD * DINNER / 4);
    round4<<<(SCD * DINNER / 4 + 255) / 256, blk>>>(Wk, Wkp, SCD * DINNER / 4);
    round4<<<(SCD * DINNER / 4 + 255) / 256, blk>>>(Wv, Wvp, SCD * DINNER / 4);
    round4<<<(DINNER * SQD / 4 + 255) / 256, blk>>>(Wo, Wop, DINNER * SQD / 4);

    gemm_tf32<<<gProj, blk, GEMM_SMEM>>>(Xb, Wqp, Qb, nullptr, MROWS, DINNER, SQD, 1);
    gemm_tf32<<<gProj, blk, GEMM_SMEM>>>(Cb, Wkp, Kb, nullptr, MROWS, DINNER, SCD, 2);
    gemm_tf32<<<gProj, blk, GEMM_SMEM>>>(Cb, Wvp, Vb, nullptr, MROWS, DINNER, SCD, 2);
    flash_attn<<<dim3(SQL / 256, NHEADS, NB), blk, ATT_SMEM>>>(Qb, Kb, Vb, Ab);
    gemm_tf32<<<dim3(SQD / GBN, MROWS / GBM), blk, GEMM_SMEM>>>(
        Ab, Wop, out, bo, MROWS, SQD, DINNER, 0);
}